// round 2
// baseline (speedup 1.0000x reference)
#include <cuda_runtime.h>

#define NN    64
#define CC    128
#define HWP   3136          // 56*56
#define MTOT  200704        // NN*HWP
#define EPSI  1e-5f
#define TITER 10
#define NSB   128
#define GCHUNK 784          // HWP/4
#define GT    (GCHUNK/16)   // 49 k-tiles
#define GBLK  256

#define GRAM_SMEM (2*16*132*4 + 2*16*128*8)   // 49664
#define WHIT_SMEM (CC*CC*4 + 2*16*128*8)      // 98304
#define NS_SMEM   (2*CC*CC*4)                 // 131072

// ---------------- scratch (device globals; no allocation) ----------------
__device__ float d_gpart[GBLK * CC * CC];   // 16 MB partial gram tiles
__device__ float d_cpart[GBLK * CC];
__device__ float d_gram[CC * CC];
__device__ float d_chsum[CC];
__device__ float d_Sig[CC * CC];
__device__ float d_P2[2][CC * CC];
__device__ float d_wmT[CC * CC];
__device__ float d_bias2[CC];
__device__ float d_trace;
__device__ unsigned g_bar;

// ---------------- packed fp32x2 helpers (sm_103a dual-FMA) ----------------
__device__ __forceinline__ unsigned long long pk(float lo, float hi) {
    unsigned long long r;
    asm("mov.b64 %0, {%1, %2};" : "=l"(r) : "f"(lo), "f"(hi));
    return r;
}
__device__ __forceinline__ void unpk(unsigned long long v, float &lo, float &hi) {
    asm("mov.b64 {%0, %1}, %2;" : "=f"(lo), "=f"(hi) : "l"(v));
}
__device__ __forceinline__ void fma2(unsigned long long &d, unsigned long long a, unsigned long long b) {
    asm("fma.rn.f32x2 %0, %1, %2, %0;" : "+l"(d) : "l"(a), "l"(b));
}

// ---------------- kernel 0: reset barrier + trace ----------------
__global__ void zero_kernel() {
    if (threadIdx.x == 0) { d_trace = 0.f; g_bar = 0u; }
}

// ---------------- kernel 1: Gram partials + channel-sum partials ----------------
// 256 blocks = 64 n x 4 chunks(784). Double-buffered smem, 1 sync/tile.
// a-operand: As[k][c] (c contig, broadcast across lanes). b: duplicated pairs.
__global__ void __launch_bounds__(256, 2) gram_kernel(const float* __restrict__ X) {
    extern __shared__ char smraw[];
    float* As = (float*)smraw;                                        // 2 x 16*132
    unsigned long long* Bs2 = (unsigned long long*)(smraw + 2*16*132*4); // 2 x 16*128
    __shared__ float chs[CC];
    const int tid = threadIdx.x;
    const int n = blockIdx.x >> 2;
    const int pbase = (blockIdx.x & 3) * GCHUNK;
    const float* Xn = X + (size_t)n * (CC * HWP) + pbase;

    const int cL = tid >> 2;           // 0..63 (and +64)
    const int q0 = (tid & 3) * 4;      // k sub-offset
    const int ty = tid >> 5;           // 0..7
    const int tx = tid & 31;           // 0..31

    if (tid < CC) chs[tid] = 0.f;
    unsigned long long acc[8][4];
#pragma unroll
    for (int i = 0; i < 8; i++)
#pragma unroll
        for (int j = 0; j < 4; j++) acc[i][j] = 0ull;
    float cs0 = 0.f, cs1 = 0.f;

    // preload + stage tile 0
    float4 v0 = *(const float4*)(Xn + (size_t)cL * HWP + q0);
    float4 v1 = *(const float4*)(Xn + (size_t)(cL + 64) * HWP + q0);
    {
        float* A = As;
        unsigned long long* B = Bs2;
        A[(q0+0)*132 + cL] = v0.x; A[(q0+1)*132 + cL] = v0.y;
        A[(q0+2)*132 + cL] = v0.z; A[(q0+3)*132 + cL] = v0.w;
        A[(q0+0)*132 + cL+64] = v1.x; A[(q0+1)*132 + cL+64] = v1.y;
        A[(q0+2)*132 + cL+64] = v1.z; A[(q0+3)*132 + cL+64] = v1.w;
        B[(q0+0)*128 + cL] = pk(v0.x, v0.x); B[(q0+1)*128 + cL] = pk(v0.y, v0.y);
        B[(q0+2)*128 + cL] = pk(v0.z, v0.z); B[(q0+3)*128 + cL] = pk(v0.w, v0.w);
        B[(q0+0)*128 + cL+64] = pk(v1.x, v1.x); B[(q0+1)*128 + cL+64] = pk(v1.y, v1.y);
        B[(q0+2)*128 + cL+64] = pk(v1.z, v1.z); B[(q0+3)*128 + cL+64] = pk(v1.w, v1.w);
        cs0 += (v0.x + v0.y) + (v0.z + v0.w);
        cs1 += (v1.x + v1.y) + (v1.z + v1.w);
    }
    __syncthreads();

    for (int t = 0; t < GT; ++t) {
        const int cur = t & 1;
        float4 nv0, nv1;
        if (t + 1 < GT) {
            nv0 = *(const float4*)(Xn + (size_t)cL * HWP + (t+1)*16 + q0);
            nv1 = *(const float4*)(Xn + (size_t)(cL + 64) * HWP + (t+1)*16 + q0);
        }
        const float* A = As + cur * (16*132);
        const unsigned long long* B = Bs2 + cur * (16*128);
#pragma unroll
        for (int k = 0; k < 16; ++k) {
            const ulonglong2* wp = (const ulonglong2*)(A + k*132 + ty*16);
            ulonglong2 aA = wp[0], aB = wp[1], aC = wp[2], aD = wp[3];
            const ulonglong2* xp = (const ulonglong2*)(B + k*128 + tx*4);
            ulonglong2 b01 = xp[0], b23 = xp[1];
            unsigned long long ap[8] = {aA.x, aA.y, aB.x, aB.y, aC.x, aC.y, aD.x, aD.y};
#pragma unroll
            for (int ip = 0; ip < 8; ip++) {
                fma2(acc[ip][0], ap[ip], b01.x);
                fma2(acc[ip][1], ap[ip], b01.y);
                fma2(acc[ip][2], ap[ip], b23.x);
                fma2(acc[ip][3], ap[ip], b23.y);
            }
        }
        if (t + 1 < GT) {
            float* A2 = As + (1-cur) * (16*132);
            unsigned long long* B2 = Bs2 + (1-cur) * (16*128);
            A2[(q0+0)*132 + cL] = nv0.x; A2[(q0+1)*132 + cL] = nv0.y;
            A2[(q0+2)*132 + cL] = nv0.z; A2[(q0+3)*132 + cL] = nv0.w;
            A2[(q0+0)*132 + cL+64] = nv1.x; A2[(q0+1)*132 + cL+64] = nv1.y;
            A2[(q0+2)*132 + cL+64] = nv1.z; A2[(q0+3)*132 + cL+64] = nv1.w;
            B2[(q0+0)*128 + cL] = pk(nv0.x, nv0.x); B2[(q0+1)*128 + cL] = pk(nv0.y, nv0.y);
            B2[(q0+2)*128 + cL] = pk(nv0.z, nv0.z); B2[(q0+3)*128 + cL] = pk(nv0.w, nv0.w);
            B2[(q0+0)*128 + cL+64] = pk(nv1.x, nv1.x); B2[(q0+1)*128 + cL+64] = pk(nv1.y, nv1.y);
            B2[(q0+2)*128 + cL+64] = pk(nv1.z, nv1.z); B2[(q0+3)*128 + cL+64] = pk(nv1.w, nv1.w);
            cs0 += (nv0.x + nv0.y) + (nv0.z + nv0.w);
            cs1 += (nv1.x + nv1.y) + (nv1.z + nv1.w);
        }
        __syncthreads();
    }

    atomicAdd(&chs[cL], cs0);
    atomicAdd(&chs[cL + 64], cs1);
    __syncthreads();
    if (tid < CC) d_cpart[blockIdx.x * CC + tid] = chs[tid];
    float* gp = d_gpart + (size_t)blockIdx.x * (CC * CC);
#pragma unroll
    for (int ip = 0; ip < 8; ip++) {
        int r0 = ty*16 + 2*ip;
        float l0, h0, l1, h1, l2, h2, l3, h3;
        unpk(acc[ip][0], l0, h0); unpk(acc[ip][1], l1, h1);
        unpk(acc[ip][2], l2, h2); unpk(acc[ip][3], l3, h3);
        *(float4*)(gp + r0*CC + tx*4)     = make_float4(l0, l1, l2, l3);
        *(float4*)(gp + (r0+1)*CC + tx*4) = make_float4(h0, h1, h2, h3);
    }
}

// ---------------- kernel 2: reduce partials ----------------
__global__ void reduce_kernel() {
    const int bid = blockIdx.x, tid = threadIdx.x;
    if (bid < 64) {
        const int i = bid * 256 + tid;
        float s = 0.f;
#pragma unroll 8
        for (int b = 0; b < GBLK; b++) s += d_gpart[(size_t)b * (CC*CC) + i];
        d_gram[i] = s;
    } else {
        if (tid < CC) {
            float s = 0.f;
#pragma unroll 8
            for (int b = 0; b < GBLK; b++) s += d_cpart[b * CC + tid];
            d_chsum[tid] = s;
        }
    }
}

// ---------------- kernel 3: Newton-Schulz (smem-staged, ping-pong, 1 barrier/iter) --
__device__ __forceinline__ void gsync(unsigned &tgt) {
    __threadfence();
    __syncthreads();
    tgt += NSB;
    if (threadIdx.x == 0) {
        atomicAdd(&g_bar, 1u);
        while (*(volatile unsigned*)&g_bar < tgt) {}
    }
    __syncthreads();
}

__global__ void __launch_bounds__(128, 1) ns_kernel(const float* __restrict__ beta) {
    extern __shared__ float dsm[];
    float* Sig_s = dsm;            // 16384 floats
    float* P_s   = dsm + CC*CC;    // 16384 floats
    __shared__ float mean_s[CC], pr_s[CC], t1_s[CC], t2_s[CC];
    __shared__ float rtr_s;
    const int r = blockIdx.x, j = threadIdx.x;

    mean_s[j] = d_chsum[j] * (1.f / (float)MTOT);
    __syncthreads();

    float sig = d_gram[r*CC + j] * (1.f / (float)MTOT) - mean_s[r] * mean_s[j]
                + ((j == r) ? EPSI : 0.f);
    __stcg(&d_Sig[r*CC + j], sig);
    __stcg(&d_P2[0][r*CC + j], (j == r) ? 1.f : 0.f);
    if (j == r) atomicAdd(&d_trace, sig);

    unsigned tgt = 0;
    gsync(tgt);

    if (j == 0) rtr_s = 1.f / *(volatile float*)&d_trace;
    {   // stage Sigma once
        const float4* Sg = (const float4*)d_Sig;
        float4* Ss = (float4*)Sig_s;
        for (int i = j; i < CC*CC/4; i += CC) Ss[i] = __ldcg(Sg + i);
    }
    __syncthreads();
    const float rtr = rtr_s;

    int cur = 0;
    for (int it = 0; it < TITER; ++it) {
        {   // stage current P
            const float4* Pg = (const float4*)d_P2[cur];
            float4* Ps4 = (float4*)P_s;
            for (int i = j; i < CC*CC/4; i += CC) Ps4[i] = __ldcg(Pg + i);
        }
        __syncthreads();
        float prj = P_s[r*CC + j];
        pr_s[j] = prj;
        __syncthreads();
        float a = 0.f;
#pragma unroll
        for (int k = 0; k < CC; k += 4) {
            float4 pv = *(const float4*)(pr_s + k);
            a = fmaf(pv.x, P_s[(k+0)*CC + j], a);
            a = fmaf(pv.y, P_s[(k+1)*CC + j], a);
            a = fmaf(pv.z, P_s[(k+2)*CC + j], a);
            a = fmaf(pv.w, P_s[(k+3)*CC + j], a);
        }
        t1_s[j] = a;
        __syncthreads();
        float b = 0.f;
#pragma unroll
        for (int k = 0; k < CC; k += 4) {
            float4 pv = *(const float4*)(t1_s + k);
            b = fmaf(pv.x, P_s[(k+0)*CC + j], b);
            b = fmaf(pv.y, P_s[(k+1)*CC + j], b);
            b = fmaf(pv.z, P_s[(k+2)*CC + j], b);
            b = fmaf(pv.w, P_s[(k+3)*CC + j], b);
        }
        t2_s[j] = b;
        __syncthreads();
        float u = 0.f;
#pragma unroll
        for (int k = 0; k < CC; k += 4) {
            float4 pv = *(const float4*)(t2_s + k);
            u = fmaf(pv.x, Sig_s[(k+0)*CC + j], u);
            u = fmaf(pv.y, Sig_s[(k+1)*CC + j], u);
            u = fmaf(pv.z, Sig_s[(k+2)*CC + j], u);
            u = fmaf(pv.w, Sig_s[(k+3)*CC + j], u);
        }
        __stcg(&d_P2[1 - cur][r*CC + j], 1.5f * prj - 0.5f * rtr * u);
        gsync(tgt);
        cur ^= 1;
    }

    float w = __ldcg(&d_P2[cur][r*CC + j]) * sqrtf(rtr);
    d_wmT[j*CC + r] = w;
    t1_s[j] = w * mean_s[j];
    __syncthreads();
    for (int s = 64; s > 0; s >>= 1) {
        if (j < s) t1_s[j] += t1_s[j + s];
        __syncthreads();
    }
    if (j == 0) d_bias2[r] = beta[r] - t1_s[0];
}

// ---------------- kernel 4: whitening GEMM Y = wm @ Xc + bias' ----------------
// Full wmT resident in smem; X tiles double-buffered (dup pairs), 1 sync/tile.
__global__ void __launch_bounds__(256, 2) whit_kernel(const float* __restrict__ X,
                                                      float* __restrict__ Y) {
    extern __shared__ char smraw[];
    float* Ws = (float*)smraw;                                      // 128x128
    unsigned long long* Xs2 = (unsigned long long*)(smraw + CC*CC*4); // 2 x 16*128
    __shared__ float bias_s[CC];
    const int tid = threadIdx.x;
    const int pt = blockIdx.x % 49;
    const int np = blockIdx.x / 49;
    const int p0 = pt * 64;
    const float* Xa = X + (size_t)np * (CC * HWP) + p0;
    const float* Xb = X + (size_t)(np + 32) * (CC * HWP) + p0;
    float* Ya = Y + (size_t)np * (CC * HWP) + p0;
    float* Yb = Y + (size_t)(np + 32) * (CC * HWP) + p0;

    if (tid < CC) bias_s[tid] = d_bias2[tid];
    {   // load full wmT once
        const float4* Wg = (const float4*)d_wmT;
        float4* Wsm = (float4*)Ws;
#pragma unroll
        for (int i = tid; i < CC*CC/4; i += 256) Wsm[i] = Wg[i];
    }
    const int ty = tid >> 5, tx = tid & 31;
    const int kkA = tid >> 5;          // 0..7
    const int gA = tid & 31;

    unsigned long long acc[8][4];
#pragma unroll
    for (int i = 0; i < 8; i++)
#pragma unroll
        for (int jj = 0; jj < 4; jj++) acc[i][jj] = 0ull;

    const float* s0 = (gA < 16) ? (Xa + (size_t)kkA * HWP + gA*4)
                                : (Xb + (size_t)kkA * HWP + (gA-16)*4);
    const float* s1 = (gA < 16) ? (Xa + (size_t)(kkA+8) * HWP + gA*4)
                                : (Xb + (size_t)(kkA+8) * HWP + (gA-16)*4);
    // preload + stage tile 0
    float4 x0 = *(const float4*)s0;
    float4 x1 = *(const float4*)s1;
    {
        ulonglong2* dst0 = (ulonglong2*)(Xs2 + kkA*128 + gA*4);
        dst0[0] = make_ulonglong2(pk(x0.x, x0.x), pk(x0.y, x0.y));
        dst0[1] = make_ulonglong2(pk(x0.z, x0.z), pk(x0.w, x0.w));
        ulonglong2* dst1 = (ulonglong2*)(Xs2 + (kkA+8)*128 + gA*4);
        dst1[0] = make_ulonglong2(pk(x1.x, x1.x), pk(x1.y, x1.y));
        dst1[1] = make_ulonglong2(pk(x1.z, x1.z), pk(x1.w, x1.w));
    }
    __syncthreads();

    for (int t = 0; t < 8; ++t) {
        const int cur = t & 1;
        float4 nx0, nx1;
        if (t < 7) {
            nx0 = *(const float4*)(s0 + (size_t)(t+1)*16*HWP);
            nx1 = *(const float4*)(s1 + (size_t)(t+1)*16*HWP);
        }
        const unsigned long long* B = Xs2 + cur * (16*128);
#pragma unroll
        for (int k = 0; k < 16; ++k) {
            const int kg = t*16 + k;
            const ulonglong2* wp = (const ulonglong2*)(Ws + kg*CC + ty*16);
            ulonglong2 aA = wp[0], aB = wp[1], aC = wp[2], aD = wp[3];
            const ulonglong2* xp = (const ulonglong2*)(B + k*128 + tx*4);
            ulonglong2 b01 = xp[0], b23 = xp[1];
            unsigned long long ap[8] = {aA.x, aA.y, aB.x, aB.y, aC.x, aC.y, aD.x, aD.y};
#pragma unroll
            for (int ip = 0; ip < 8; ip++) {
                fma2(acc[ip][0], ap[ip], b01.x);
                fma2(acc[ip][1], ap[ip], b01.y);
                fma2(acc[ip][2], ap[ip], b23.x);
                fma2(acc[ip][3], ap[ip], b23.y);
            }
        }
        if (t < 7) {
            unsigned long long* B2 = Xs2 + (1-cur) * (16*128);
            ulonglong2* dst0 = (ulonglong2*)(B2 + kkA*128 + gA*4);
            dst0[0] = make_ulonglong2(pk(nx0.x, nx0.x), pk(nx0.y, nx0.y));
            dst0[1] = make_ulonglong2(pk(nx0.z, nx0.z), pk(nx0.w, nx0.w));
            ulonglong2* dst1 = (ulonglong2*)(B2 + (kkA+8)*128 + gA*4);
            dst1[0] = make_ulonglong2(pk(nx1.x, nx1.x), pk(nx1.y, nx1.y));
            dst1[1] = make_ulonglong2(pk(nx1.z, nx1.z), pk(nx1.w, nx1.w));
        }
        __syncthreads();
    }

    float* baseY = (tx < 16) ? Ya : Yb;
    const int off = (tx < 16) ? tx*4 : (tx-16)*4;
#pragma unroll
    for (int ip = 0; ip < 8; ip++) {
        float l0, h0, l1, h1, l2, h2, l3, h3;
        unpk(acc[ip][0], l0, h0); unpk(acc[ip][1], l1, h1);
        unpk(acc[ip][2], l2, h2); unpk(acc[ip][3], l3, h3);
        const int r0 = ty*16 + 2*ip;
        const float b0 = bias_s[r0], b1 = bias_s[r0 + 1];
        *(float4*)(baseY + (size_t)r0 * HWP + off)     = make_float4(l0+b0, l1+b0, l2+b0, l3+b0);
        *(float4*)(baseY + (size_t)(r0+1) * HWP + off) = make_float4(h0+b1, h1+b1, h2+b1, h3+b1);
    }
}

// ---------------- launch ----------------
extern "C" void kernel_launch(void* const* d_in, const int* in_sizes, int n_in,
                              void* d_out, int out_size) {
    const float* X = (const float*)d_in[0];
    const float* beta = (const float*)d_in[1];
    float* Y = (float*)d_out;
    cudaFuncSetAttribute(gram_kernel, cudaFuncAttributeMaxDynamicSharedMemorySize, GRAM_SMEM);
    cudaFuncSetAttribute(ns_kernel,   cudaFuncAttributeMaxDynamicSharedMemorySize, NS_SMEM);
    cudaFuncSetAttribute(whit_kernel, cudaFuncAttributeMaxDynamicSharedMemorySize, WHIT_SMEM);
    zero_kernel<<<1, 32>>>();
    gram_kernel<<<GBLK, 256, GRAM_SMEM>>>(X);
    reduce_kernel<<<65, 256>>>();
    ns_kernel<<<NSB, 128, NS_SMEM>>>(beta);
    whit_kernel<<<49 * 32, 256, WHIT_SMEM>>>(X, Y);
}

// round 3
// speedup vs baseline: 1.2253x; 1.2253x over previous
#include <cuda_runtime.h>

#define NN    64
#define CC    128
#define HWP   3136          // 56*56
#define MTOT  200704        // NN*HWP
#define EPSI  1e-5f
#define TITER 10
#define NSB   32
#define GCHUNK 784          // HWP/4
#define GT    (GCHUNK/16)   // 49 k-tiles
#define GBLK  256

#define GRAM_SMEM (4*2048*4 + 2*16*132*4)     // 32768 + 16896 = 49664
#define WHIT_SMEM (CC*CC*4 + 3*2048*4)        // 65536 + 24576 = 90112
#define NS_SMEM   (2*CC*CC*4)                 // 131072

// ---------------- scratch (device globals; no allocation) ----------------
__device__ float d_gpart[GBLK * CC * CC];   // 16 MB partial gram tiles
__device__ float d_cpart[GBLK * CC];
__device__ float d_gram[CC * CC];
__device__ float d_chsum[CC];
__device__ float d_Sig[CC * CC];
__device__ float d_P2[2][CC * CC];
__device__ float d_wmT[CC * CC];
__device__ float d_bias2[CC];
__device__ float d_trace;
__device__ unsigned g_bar;

// ---------------- packed fp32x2 helpers (sm_103a dual-FMA) ----------------
__device__ __forceinline__ unsigned long long pk(float lo, float hi) {
    unsigned long long r;
    asm("mov.b64 %0, {%1, %2};" : "=l"(r) : "f"(lo), "f"(hi));
    return r;
}
__device__ __forceinline__ void unpk(unsigned long long v, float &lo, float &hi) {
    asm("mov.b64 {%0, %1}, %2;" : "=f"(lo), "=f"(hi) : "l"(v));
}
__device__ __forceinline__ void fma2(unsigned long long &d, unsigned long long a, unsigned long long b) {
    asm("fma.rn.f32x2 %0, %1, %2, %0;" : "+l"(d) : "l"(a), "l"(b));
}

// ---------------- cp.async helpers ----------------
__device__ __forceinline__ void cpa16(unsigned d, const float* s) {
    asm volatile("cp.async.cg.shared.global [%0], [%1], 16;" :: "r"(d), "l"(s));
}
__device__ __forceinline__ void cpcommit() { asm volatile("cp.async.commit_group;"); }
template<int N> __device__ __forceinline__ void cpwait() {
    asm volatile("cp.async.wait_group %0;" :: "n"(N));
}

// ---------------- kernel 0: reset barrier + trace ----------------
__global__ void zero_kernel() {
    if (threadIdx.x == 0) { d_trace = 0.f; g_bar = 0u; }
}

// ---------------- kernel 1: Gram partials (cp.async pipelined) ----------------
// 256 blocks = 64 n x 4 chunks(784). 4 raw stages [c][16] + 2 transposed As[k][c].
// raw elements are strictly per-thread -> only 1 __syncthreads per tile.
__global__ void __launch_bounds__(256, 2) gram_kernel(const float* __restrict__ X) {
    extern __shared__ char smraw[];
    float* raw = (float*)smraw;                      // 4 x 2048 floats
    float* As  = (float*)(smraw + 4 * 2048 * 4);     // 2 x 16*132 floats
    __shared__ float chs[CC];
    const int tid = threadIdx.x;
    const int n = blockIdx.x >> 2;
    const int pbase = (blockIdx.x & 3) * GCHUNK;
    const float* Xn = X + (size_t)n * (CC * HWP) + pbase;

    const int cL = tid >> 2;           // 0..63 (and +64)
    const int q0 = (tid & 3) * 4;      // k sub-offset within 16
    const int ty = tid >> 5;           // 0..7
    const int tx = tid & 31;           // 0..31

    if (tid < CC) chs[tid] = 0.f;
    unsigned long long acc[8][4];
#pragma unroll
    for (int i = 0; i < 8; i++)
#pragma unroll
        for (int j = 0; j < 4; j++) acc[i][j] = 0ull;
    float cs0 = 0.f, cs1 = 0.f;

    const float* g0 = Xn + (size_t)cL * HWP + q0;
    const float* g1 = Xn + (size_t)(cL + 64) * HWP + q0;
    unsigned rbase;
    {
        unsigned long long a64 = __cvta_generic_to_shared(raw);
        rbase = (unsigned)a64;
    }
    const unsigned r_off0 = (cL * 16 + q0) * 4;
    const unsigned r_off1 = ((cL + 64) * 16 + q0) * 4;

    // prologue: fill 4 raw stages
#pragma unroll
    for (int t = 0; t < 4; ++t) {
        unsigned b = rbase + (unsigned)(t * 2048 * 4);
        cpa16(b + r_off0, g0 + t * 16);
        cpa16(b + r_off1, g1 + t * 16);
        cpcommit();
    }
    cpwait<3>();   // tile 0 ready (own data)
    {   // transpose tile 0 -> As[0]
        const float* rb = raw;
        float4 v0 = *(const float4*)(rb + cL * 16 + q0);
        float4 v1 = *(const float4*)(rb + (cL + 64) * 16 + q0);
        float* A = As;
        A[(q0+0)*132 + cL] = v0.x; A[(q0+1)*132 + cL] = v0.y;
        A[(q0+2)*132 + cL] = v0.z; A[(q0+3)*132 + cL] = v0.w;
        A[(q0+0)*132 + cL+64] = v1.x; A[(q0+1)*132 + cL+64] = v1.y;
        A[(q0+2)*132 + cL+64] = v1.z; A[(q0+3)*132 + cL+64] = v1.w;
        cs0 += (v0.x + v0.y) + (v0.z + v0.w);
        cs1 += (v1.x + v1.y) + (v1.z + v1.w);
    }
    __syncthreads();

    for (int t = 0; t < GT; ++t) {
        cpwait<2>();                         // tile t+1 ready (own data)
        if (t + 1 < GT) {                    // transpose t+1 -> As[(t+1)&1]
            const float* rb = raw + ((t + 1) & 3) * 2048;
            float4 v0 = *(const float4*)(rb + cL * 16 + q0);
            float4 v1 = *(const float4*)(rb + (cL + 64) * 16 + q0);
            float* A = As + ((t + 1) & 1) * (16 * 132);
            A[(q0+0)*132 + cL] = v0.x; A[(q0+1)*132 + cL] = v0.y;
            A[(q0+2)*132 + cL] = v0.z; A[(q0+3)*132 + cL] = v0.w;
            A[(q0+0)*132 + cL+64] = v1.x; A[(q0+1)*132 + cL+64] = v1.y;
            A[(q0+2)*132 + cL+64] = v1.z; A[(q0+3)*132 + cL+64] = v1.w;
            cs0 += (v0.x + v0.y) + (v0.z + v0.w);
            cs1 += (v1.x + v1.y) + (v1.z + v1.w);
        }
        if (t + 4 < GT) {                    // refill raw[t&3] (read at iter t-1)
            unsigned b = rbase + (unsigned)((t & 3) * 2048 * 4);
            cpa16(b + r_off0, g0 + (t + 4) * 16);
            cpa16(b + r_off1, g1 + (t + 4) * 16);
        }
        cpcommit();
        const float* A = As + (t & 1) * (16 * 132);
#pragma unroll
        for (int k = 0; k < 16; ++k) {
            const float* row = A + k * 132;
            const ulonglong2* wp = (const ulonglong2*)(row + ty * 16);
            ulonglong2 aA = wp[0], aB = wp[1], aC = wp[2], aD = wp[3];
            float4 bv = *(const float4*)(row + tx * 4);
            unsigned long long b0 = pk(bv.x, bv.x);
            unsigned long long b1 = pk(bv.y, bv.y);
            unsigned long long b2 = pk(bv.z, bv.z);
            unsigned long long b3 = pk(bv.w, bv.w);
            unsigned long long ap[8] = {aA.x, aA.y, aB.x, aB.y, aC.x, aC.y, aD.x, aD.y};
#pragma unroll
            for (int ip = 0; ip < 8; ip++) {
                fma2(acc[ip][0], ap[ip], b0);
                fma2(acc[ip][1], ap[ip], b1);
                fma2(acc[ip][2], ap[ip], b2);
                fma2(acc[ip][3], ap[ip], b3);
            }
        }
        __syncthreads();
    }

    atomicAdd(&chs[cL], cs0);
    atomicAdd(&chs[cL + 64], cs1);
    __syncthreads();
    if (tid < CC) d_cpart[blockIdx.x * CC + tid] = chs[tid];
    float* gp = d_gpart + (size_t)blockIdx.x * (CC * CC);
#pragma unroll
    for (int ip = 0; ip < 8; ip++) {
        int r0 = ty * 16 + 2 * ip;
        float l0, h0, l1, h1, l2, h2, l3, h3;
        unpk(acc[ip][0], l0, h0); unpk(acc[ip][1], l1, h1);
        unpk(acc[ip][2], l2, h2); unpk(acc[ip][3], l3, h3);
        *(float4*)(gp + r0 * CC + tx * 4)       = make_float4(l0, l1, l2, l3);
        *(float4*)(gp + (r0 + 1) * CC + tx * 4) = make_float4(h0, h1, h2, h3);
    }
}

// ---------------- kernel 2: reduce partials ----------------
__global__ void reduce_kernel() {
    const int bid = blockIdx.x, tid = threadIdx.x;
    if (bid < 64) {
        const int i = bid * 256 + tid;
        float s = 0.f;
#pragma unroll 8
        for (int b = 0; b < GBLK; b++) s += d_gpart[(size_t)b * (CC * CC) + i];
        d_gram[i] = s;
    } else {
        if (tid < CC) {
            float s = 0.f;
#pragma unroll 8
            for (int b = 0; b < GBLK; b++) s += d_cpart[b * CC + tid];
            d_chsum[tid] = s;
        }
    }
}

// ---------------- kernel 3: Newton-Schulz, 32 blocks x 512 thr (4 rows/blk) ----
__device__ __forceinline__ void gsync(unsigned &tgt) {
    __threadfence();
    __syncthreads();
    tgt += NSB;
    if (threadIdx.x == 0) {
        atomicAdd(&g_bar, 1u);
        while (*(volatile unsigned*)&g_bar < tgt) {}
    }
    __syncthreads();
}

__device__ __forceinline__ float dot128(const float* __restrict__ v,
                                        const float* __restrict__ M, int j) {
    float a0 = 0.f, a1 = 0.f, a2 = 0.f, a3 = 0.f;
#pragma unroll
    for (int k = 0; k < CC; k += 4) {
        float4 pv = *(const float4*)(v + k);
        a0 = fmaf(pv.x, M[(k + 0) * CC + j], a0);
        a1 = fmaf(pv.y, M[(k + 1) * CC + j], a1);
        a2 = fmaf(pv.z, M[(k + 2) * CC + j], a2);
        a3 = fmaf(pv.w, M[(k + 3) * CC + j], a3);
    }
    return (a0 + a1) + (a2 + a3);
}

__global__ void __launch_bounds__(512, 1) ns_kernel(const float* __restrict__ beta) {
    extern __shared__ float dsm[];
    float* Sig_s = dsm;            // 16384 floats
    float* P_s   = dsm + CC * CC;  // 16384 floats
    __shared__ float mean_s[CC];
    __shared__ float vr[4][CC], v1[4][CC], v2[4][CC];
    __shared__ float rtr_s;
    const int tid = threadIdx.x;
    const int ri = tid >> 7;           // 0..3
    const int j = tid & 127;
    const int r = blockIdx.x * 4 + ri;

    if (tid < CC) mean_s[tid] = d_chsum[tid] * (1.f / (float)MTOT);
    __syncthreads();

    float sig = d_gram[r * CC + j] * (1.f / (float)MTOT) - mean_s[r] * mean_s[j]
                + ((j == r) ? EPSI : 0.f);
    __stcg(&d_Sig[r * CC + j], sig);
    __stcg(&d_P2[0][r * CC + j], (j == r) ? 1.f : 0.f);
    if (j == r) atomicAdd(&d_trace, sig);

    unsigned tgt = 0;
    gsync(tgt);

    if (tid == 0) rtr_s = 1.f / *(volatile float*)&d_trace;
    {   // stage Sigma once
        const float4* Sg = (const float4*)d_Sig;
        float4* Ss = (float4*)Sig_s;
        for (int i = tid; i < CC * CC / 4; i += 512) Ss[i] = __ldcg(Sg + i);
    }
    __syncthreads();
    const float rtr = rtr_s;

    int cur = 0;
    for (int it = 0; it < TITER; ++it) {
        {   // stage current P
            const float4* Pg = (const float4*)d_P2[cur];
            float4* Ps = (float4*)P_s;
            for (int i = tid; i < CC * CC / 4; i += 512) Ps[i] = __ldcg(Pg + i);
        }
        __syncthreads();
        float prj = P_s[r * CC + j];
        vr[ri][j] = prj;
        __syncthreads();
        v1[ri][j] = dot128(vr[ri], P_s, j);     // T1 = P@P (row r)
        __syncthreads();
        v2[ri][j] = dot128(v1[ri], P_s, j);     // T2 = T1@P (row r)
        __syncthreads();
        float u = dot128(v2[ri], Sig_s, j);     // U = T2@Sigma (row r)
        __stcg(&d_P2[1 - cur][r * CC + j], 1.5f * prj - 0.5f * rtr * u);
        gsync(tgt);
        cur ^= 1;
    }

    float w = __ldcg(&d_P2[cur][r * CC + j]) * sqrtf(rtr);
    d_wmT[j * CC + r] = w;
    v1[ri][j] = w * mean_s[j];
    __syncthreads();
    for (int s = 64; s > 0; s >>= 1) {
        if (j < s) v1[ri][j] += v1[ri][j + s];
        __syncthreads();
    }
    if (j == 0) d_bias2[r] = beta[r] - v1[ri][0];
}

// ---------------- kernel 4: whitening GEMM (cp.async, 3-stage) ----------------
__global__ void __launch_bounds__(256, 2) whit_kernel(const float* __restrict__ X,
                                                      float* __restrict__ Y) {
    extern __shared__ char smraw[];
    float* Ws = (float*)smraw;                      // 128x128
    float* Xs = (float*)(smraw + CC * CC * 4);      // 3 x 16*128
    __shared__ float bias_s[CC];
    const int tid = threadIdx.x;
    const int pt = blockIdx.x % 49;
    const int np = blockIdx.x / 49;
    const int p0 = pt * 64;
    const float* Xa = X + (size_t)np * (CC * HWP) + p0;
    const float* Xb = X + (size_t)(np + 32) * (CC * HWP) + p0;
    float* Ya = Y + (size_t)np * (CC * HWP) + p0;
    float* Yb = Y + (size_t)(np + 32) * (CC * HWP) + p0;

    const int ty = tid >> 5, tx = tid & 31;
    const int kkA = tid >> 5;          // 0..7
    const int gA = tid & 31;

    const float* s0 = (gA < 16) ? (Xa + (size_t)kkA * HWP + gA * 4)
                                : (Xb + (size_t)kkA * HWP + (gA - 16) * 4);
    const float* s1 = (gA < 16) ? (Xa + (size_t)(kkA + 8) * HWP + gA * 4)
                                : (Xb + (size_t)(kkA + 8) * HWP + (gA - 16) * 4);
    unsigned xb;
    {
        unsigned long long a64 = __cvta_generic_to_shared(Xs);
        xb = (unsigned)a64;
    }
    const unsigned x_off0 = (kkA * 128 + gA * 4) * 4;
    const unsigned x_off1 = ((kkA + 8) * 128 + gA * 4) * 4;

    // prologue: 3 stages in flight
#pragma unroll
    for (int t = 0; t < 3; ++t) {
        unsigned b = xb + (unsigned)(t * 2048 * 4);
        cpa16(b + x_off0, s0 + (size_t)t * 16 * HWP);
        cpa16(b + x_off1, s1 + (size_t)t * 16 * HWP);
        cpcommit();
    }

    if (tid < CC) bias_s[tid] = d_bias2[tid];
    {   // load full wmT (overlapped with cp.async of first tiles)
        const float4* Wg = (const float4*)d_wmT;
        float4* Wsm = (float4*)Ws;
#pragma unroll
        for (int i = tid; i < CC * CC / 4; i += 256) Wsm[i] = Wg[i];
    }

    unsigned long long acc[8][4];
#pragma unroll
    for (int i = 0; i < 8; i++)
#pragma unroll
        for (int jj = 0; jj < 4; jj++) acc[i][jj] = 0ull;

    for (int t = 0; t < 8; ++t) {
        cpwait<2>();
        __syncthreads();            // tile t visible to all; Ws ready (t=0)
        const float* B = Xs + (t % 3) * 2048;
        const float* Wrow = Ws + t * 16 * CC;
#pragma unroll
        for (int k = 0; k < 16; ++k) {
            const ulonglong2* wp = (const ulonglong2*)(Wrow + k * CC + ty * 16);
            ulonglong2 aA = wp[0], aB = wp[1], aC = wp[2], aD = wp[3];
            float4 bv = *(const float4*)(B + k * 128 + tx * 4);
            unsigned long long b0 = pk(bv.x, bv.x);
            unsigned long long b1 = pk(bv.y, bv.y);
            unsigned long long b2 = pk(bv.z, bv.z);
            unsigned long long b3 = pk(bv.w, bv.w);
            unsigned long long ap[8] = {aA.x, aA.y, aB.x, aB.y, aC.x, aC.y, aD.x, aD.y};
#pragma unroll
            for (int ip = 0; ip < 8; ip++) {
                fma2(acc[ip][0], ap[ip], b0);
                fma2(acc[ip][1], ap[ip], b1);
                fma2(acc[ip][2], ap[ip], b2);
                fma2(acc[ip][3], ap[ip], b3);
            }
        }
        __syncthreads();            // all done reading buf t%3
        if (t + 3 < 8) {
            unsigned b = xb + (unsigned)((t % 3) * 2048 * 4);
            cpa16(b + x_off0, s0 + (size_t)(t + 3) * 16 * HWP);
            cpa16(b + x_off1, s1 + (size_t)(t + 3) * 16 * HWP);
        }
        cpcommit();
    }

    float* baseY = (tx < 16) ? Ya : Yb;
    const int off = (tx < 16) ? tx * 4 : (tx - 16) * 4;
#pragma unroll
    for (int ip = 0; ip < 8; ip++) {
        float l0, h0, l1, h1, l2, h2, l3, h3;
        unpk(acc[ip][0], l0, h0); unpk(acc[ip][1], l1, h1);
        unpk(acc[ip][2], l2, h2); unpk(acc[ip][3], l3, h3);
        const int r0 = ty * 16 + 2 * ip;
        const float b0 = bias_s[r0], b1 = bias_s[r0 + 1];
        *(float4*)(baseY + (size_t)r0 * HWP + off)       = make_float4(l0 + b0, l1 + b0, l2 + b0, l3 + b0);
        *(float4*)(baseY + (size_t)(r0 + 1) * HWP + off) = make_float4(h0 + b1, h1 + b1, h2 + b1, h3 + b1);
    }
}

// ---------------- launch ----------------
extern "C" void kernel_launch(void* const* d_in, const int* in_sizes, int n_in,
                              void* d_out, int out_size) {
    const float* X = (const float*)d_in[0];
    const float* beta = (const float*)d_in[1];
    float* Y = (float*)d_out;
    cudaFuncSetAttribute(gram_kernel, cudaFuncAttributeMaxDynamicSharedMemorySize, GRAM_SMEM);
    cudaFuncSetAttribute(ns_kernel,   cudaFuncAttributeMaxDynamicSharedMemorySize, NS_SMEM);
    cudaFuncSetAttribute(whit_kernel, cudaFuncAttributeMaxDynamicSharedMemorySize, WHIT_SMEM);
    zero_kernel<<<1, 32>>>();
    gram_kernel<<<GBLK, 256, GRAM_SMEM>>>(X);
    reduce_kernel<<<65, 256>>>();
    ns_kernel<<<NSB, 512, NS_SMEM>>>(beta);
    whit_kernel<<<49 * 32, 256, WHIT_SMEM>>>(X, Y);
}

// round 4
// speedup vs baseline: 1.2291x; 1.0031x over previous
#include <cuda_runtime.h>

#define NN    64
#define CC    128
#define HWP   3136          // 56*56
#define MTOT  200704        // NN*HWP
#define EPSI  1e-5f
#define TITER 10
#define NSB   32
#define GCHUNK 784          // HWP/4
#define GT    (GCHUNK/16)   // 49 k-tiles
#define GBLK  256

#define GRAM_SMEM (4*2048*4 + 2*16*132*4)     // 32768 + 16896 = 49664
#define WHIT_SMEM (CC*CC*4 + 3*2048*4)        // 65536 + 24576 = 90112
#define NS_SMEM   (2*CC*CC*4)                 // 131072

// ---------------- scratch (device globals; no allocation) ----------------
__device__ float d_gpart[GBLK * CC * CC];   // 16 MB partial gram tiles
__device__ float d_cpart[GBLK * CC];
__device__ float d_gram[CC * CC];
__device__ float d_chsum[CC];
__device__ float d_Sig[CC * CC];
__device__ float d_P2[2][CC * CC];
__device__ float d_wmT[CC * CC];
__device__ float d_bias2[CC];
__device__ float d_trace;
__device__ unsigned g_bar;

// ---------------- packed fp32x2 helpers (sm_103a dual-FMA) ----------------
__device__ __forceinline__ unsigned long long pk(float lo, float hi) {
    unsigned long long r;
    asm("mov.b64 %0, {%1, %2};" : "=l"(r) : "f"(lo), "f"(hi));
    return r;
}
__device__ __forceinline__ void unpk(unsigned long long v, float &lo, float &hi) {
    asm("mov.b64 {%0, %1}, %2;" : "=f"(lo), "=f"(hi) : "l"(v));
}
__device__ __forceinline__ void fma2(unsigned long long &d, unsigned long long a, unsigned long long b) {
    asm("fma.rn.f32x2 %0, %1, %2, %0;" : "+l"(d) : "l"(a), "l"(b));
}

// ---------------- cp.async helpers ----------------
__device__ __forceinline__ void cpa16(unsigned d, const float* s) {
    asm volatile("cp.async.cg.shared.global [%0], [%1], 16;" :: "r"(d), "l"(s));
}
__device__ __forceinline__ void cpcommit() { asm volatile("cp.async.commit_group;"); }
template<int N> __device__ __forceinline__ void cpwait() {
    asm volatile("cp.async.wait_group %0;" :: "n"(N));
}

// ---------------- kernel 0: reset barrier + trace ----------------
__global__ void zero_kernel() {
    if (threadIdx.x == 0) { d_trace = 0.f; g_bar = 0u; }
}

// ---------------- kernel 1: Gram partials (cp.async pipelined) ----------------
// 256 blocks = 64 n x 4 chunks(784). 4 raw stages [c][16] + 2 transposed As[k][c].
// raw elements are strictly per-thread -> only 1 __syncthreads per tile.
__global__ void __launch_bounds__(256, 2) gram_kernel(const float* __restrict__ X) {
    extern __shared__ char smraw[];
    float* raw = (float*)smraw;                      // 4 x 2048 floats
    float* As  = (float*)(smraw + 4 * 2048 * 4);     // 2 x 16*132 floats
    __shared__ float chs[CC];
    const int tid = threadIdx.x;
    const int n = blockIdx.x >> 2;
    const int pbase = (blockIdx.x & 3) * GCHUNK;
    const float* Xn = X + (size_t)n * (CC * HWP) + pbase;

    const int cL = tid >> 2;           // 0..63 (and +64)
    const int q0 = (tid & 3) * 4;      // k sub-offset within 16
    const int ty = tid >> 5;           // 0..7
    const int tx = tid & 31;           // 0..31

    if (tid < CC) chs[tid] = 0.f;
    unsigned long long acc[8][4];
#pragma unroll
    for (int i = 0; i < 8; i++)
#pragma unroll
        for (int j = 0; j < 4; j++) acc[i][j] = 0ull;
    float cs0 = 0.f, cs1 = 0.f;

    const float* g0 = Xn + (size_t)cL * HWP + q0;
    const float* g1 = Xn + (size_t)(cL + 64) * HWP + q0;
    unsigned rbase;
    {
        unsigned long long a64 = __cvta_generic_to_shared(raw);
        rbase = (unsigned)a64;
    }
    const unsigned r_off0 = (cL * 16 + q0) * 4;
    const unsigned r_off1 = ((cL + 64) * 16 + q0) * 4;

    // prologue: fill 4 raw stages
#pragma unroll
    for (int t = 0; t < 4; ++t) {
        unsigned b = rbase + (unsigned)(t * 2048 * 4);
        cpa16(b + r_off0, g0 + t * 16);
        cpa16(b + r_off1, g1 + t * 16);
        cpcommit();
    }
    cpwait<3>();   // tile 0 ready (own data)
    {   // transpose tile 0 -> As[0]
        const float* rb = raw;
        float4 v0 = *(const float4*)(rb + cL * 16 + q0);
        float4 v1 = *(const float4*)(rb + (cL + 64) * 16 + q0);
        float* A = As;
        A[(q0+0)*132 + cL] = v0.x; A[(q0+1)*132 + cL] = v0.y;
        A[(q0+2)*132 + cL] = v0.z; A[(q0+3)*132 + cL] = v0.w;
        A[(q0+0)*132 + cL+64] = v1.x; A[(q0+1)*132 + cL+64] = v1.y;
        A[(q0+2)*132 + cL+64] = v1.z; A[(q0+3)*132 + cL+64] = v1.w;
        cs0 += (v0.x + v0.y) + (v0.z + v0.w);
        cs1 += (v1.x + v1.y) + (v1.z + v1.w);
    }
    __syncthreads();

    for (int t = 0; t < GT; ++t) {
        cpwait<2>();                         // tile t+1 ready (own data)
        if (t + 1 < GT) {                    // transpose t+1 -> As[(t+1)&1]
            const float* rb = raw + ((t + 1) & 3) * 2048;
            float4 v0 = *(const float4*)(rb + cL * 16 + q0);
            float4 v1 = *(const float4*)(rb + (cL + 64) * 16 + q0);
            float* A = As + ((t + 1) & 1) * (16 * 132);
            A[(q0+0)*132 + cL] = v0.x; A[(q0+1)*132 + cL] = v0.y;
            A[(q0+2)*132 + cL] = v0.z; A[(q0+3)*132 + cL] = v0.w;
            A[(q0+0)*132 + cL+64] = v1.x; A[(q0+1)*132 + cL+64] = v1.y;
            A[(q0+2)*132 + cL+64] = v1.z; A[(q0+3)*132 + cL+64] = v1.w;
            cs0 += (v0.x + v0.y) + (v0.z + v0.w);
            cs1 += (v1.x + v1.y) + (v1.z + v1.w);
        }
        if (t + 4 < GT) {                    // refill raw[t&3] (read at iter t-1)
            unsigned b = rbase + (unsigned)((t & 3) * 2048 * 4);
            cpa16(b + r_off0, g0 + (t + 4) * 16);
            cpa16(b + r_off1, g1 + (t + 4) * 16);
        }
        cpcommit();
        const float* A = As + (t & 1) * (16 * 132);
#pragma unroll
        for (int k = 0; k < 16; ++k) {
            const float* row = A + k * 132;
            const ulonglong2* wp = (const ulonglong2*)(row + ty * 16);
            ulonglong2 aA = wp[0], aB = wp[1], aC = wp[2], aD = wp[3];
            float4 bv = *(const float4*)(row + tx * 4);
            unsigned long long b0 = pk(bv.x, bv.x);
            unsigned long long b1 = pk(bv.y, bv.y);
            unsigned long long b2 = pk(bv.z, bv.z);
            unsigned long long b3 = pk(bv.w, bv.w);
            unsigned long long ap[8] = {aA.x, aA.y, aB.x, aB.y, aC.x, aC.y, aD.x, aD.y};
#pragma unroll
            for (int ip = 0; ip < 8; ip++) {
                fma2(acc[ip][0], ap[ip], b0);
                fma2(acc[ip][1], ap[ip], b1);
                fma2(acc[ip][2], ap[ip], b2);
                fma2(acc[ip][3], ap[ip], b3);
            }
        }
        __syncthreads();
    }

    atomicAdd(&chs[cL], cs0);
    atomicAdd(&chs[cL + 64], cs1);
    __syncthreads();
    if (tid < CC) d_cpart[blockIdx.x * CC + tid] = chs[tid];
    float* gp = d_gpart + (size_t)blockIdx.x * (CC * CC);
#pragma unroll
    for (int ip = 0; ip < 8; ip++) {
        int r0 = ty * 16 + 2 * ip;
        float l0, h0, l1, h1, l2, h2, l3, h3;
        unpk(acc[ip][0], l0, h0); unpk(acc[ip][1], l1, h1);
        unpk(acc[ip][2], l2, h2); unpk(acc[ip][3], l3, h3);
        *(float4*)(gp + r0 * CC + tx * 4)       = make_float4(l0, l1, l2, l3);
        *(float4*)(gp + (r0 + 1) * CC + tx * 4) = make_float4(h0, h1, h2, h3);
    }
}

// ---------------- kernel 2: reduce partials ----------------
__global__ void reduce_kernel() {
    const int bid = blockIdx.x, tid = threadIdx.x;
    if (bid < 64) {
        const int i = bid * 256 + tid;
        float s = 0.f;
#pragma unroll 8
        for (int b = 0; b < GBLK; b++) s += d_gpart[(size_t)b * (CC * CC) + i];
        d_gram[i] = s;
    } else {
        if (tid < CC) {
            float s = 0.f;
#pragma unroll 8
            for (int b = 0; b < GBLK; b++) s += d_cpart[b * CC + tid];
            d_chsum[tid] = s;
        }
    }
}

// ---------------- kernel 3: Newton-Schulz, 32 blocks x 512 thr (4 rows/blk) ----
__device__ __forceinline__ void gsync(unsigned &tgt) {
    __threadfence();
    __syncthreads();
    tgt += NSB;
    if (threadIdx.x == 0) {
        atomicAdd(&g_bar, 1u);
        while (*(volatile unsigned*)&g_bar < tgt) {}
    }
    __syncthreads();
}

__device__ __forceinline__ float dot128(const float* __restrict__ v,
                                        const float* __restrict__ M, int j) {
    float a0 = 0.f, a1 = 0.f, a2 = 0.f, a3 = 0.f;
#pragma unroll
    for (int k = 0; k < CC; k += 4) {
        float4 pv = *(const float4*)(v + k);
        a0 = fmaf(pv.x, M[(k + 0) * CC + j], a0);
        a1 = fmaf(pv.y, M[(k + 1) * CC + j], a1);
        a2 = fmaf(pv.z, M[(k + 2) * CC + j], a2);
        a3 = fmaf(pv.w, M[(k + 3) * CC + j], a3);
    }
    return (a0 + a1) + (a2 + a3);
}

__global__ void __launch_bounds__(512, 1) ns_kernel(const float* __restrict__ beta) {
    extern __shared__ float dsm[];
    float* Sig_s = dsm;            // 16384 floats
    float* P_s   = dsm + CC * CC;  // 16384 floats
    __shared__ float mean_s[CC];
    __shared__ float vr[4][CC], v1[4][CC], v2[4][CC];
    __shared__ float rtr_s;
    const int tid = threadIdx.x;
    const int ri = tid >> 7;           // 0..3
    const int j = tid & 127;
    const int r = blockIdx.x * 4 + ri;

    if (tid < CC) mean_s[tid] = d_chsum[tid] * (1.f / (float)MTOT);
    __syncthreads();

    float sig = d_gram[r * CC + j] * (1.f / (float)MTOT) - mean_s[r] * mean_s[j]
                + ((j == r) ? EPSI : 0.f);
    __stcg(&d_Sig[r * CC + j], sig);
    __stcg(&d_P2[0][r * CC + j], (j == r) ? 1.f : 0.f);
    if (j == r) atomicAdd(&d_trace, sig);

    unsigned tgt = 0;
    gsync(tgt);

    if (tid == 0) rtr_s = 1.f / *(volatile float*)&d_trace;
    {   // stage Sigma once
        const float4* Sg = (const float4*)d_Sig;
        float4* Ss = (float4*)Sig_s;
        for (int i = tid; i < CC * CC / 4; i += 512) Ss[i] = __ldcg(Sg + i);
    }
    __syncthreads();
    const float rtr = rtr_s;

    int cur = 0;
    for (int it = 0; it < TITER; ++it) {
        {   // stage current P
            const float4* Pg = (const float4*)d_P2[cur];
            float4* Ps = (float4*)P_s;
            for (int i = tid; i < CC * CC / 4; i += 512) Ps[i] = __ldcg(Pg + i);
        }
        __syncthreads();
        float prj = P_s[r * CC + j];
        vr[ri][j] = prj;
        __syncthreads();
        v1[ri][j] = dot128(vr[ri], P_s, j);     // T1 = P@P (row r)
        __syncthreads();
        v2[ri][j] = dot128(v1[ri], P_s, j);     // T2 = T1@P (row r)
        __syncthreads();
        float u = dot128(v2[ri], Sig_s, j);     // U = T2@Sigma (row r)
        __stcg(&d_P2[1 - cur][r * CC + j], 1.5f * prj - 0.5f * rtr * u);
        gsync(tgt);
        cur ^= 1;
    }

    float w = __ldcg(&d_P2[cur][r * CC + j]) * sqrtf(rtr);
    d_wmT[j * CC + r] = w;
    v1[ri][j] = w * mean_s[j];
    __syncthreads();
    for (int s = 64; s > 0; s >>= 1) {
        if (j < s) v1[ri][j] += v1[ri][j + s];
        __syncthreads();
    }
    if (j == 0) d_bias2[r] = beta[r] - v1[ri][0];
}

// ---------------- kernel 4: whitening GEMM (cp.async, 3-stage) ----------------
__global__ void __launch_bounds__(256, 2) whit_kernel(const float* __restrict__ X,
                                                      float* __restrict__ Y) {
    extern __shared__ char smraw[];
    float* Ws = (float*)smraw;                      // 128x128
    float* Xs = (float*)(smraw + CC * CC * 4);      // 3 x 16*128
    __shared__ float bias_s[CC];
    const int tid = threadIdx.x;
    const int pt = blockIdx.x % 49;
    const int np = blockIdx.x / 49;
    const int p0 = pt * 64;
    const float* Xa = X + (size_t)np * (CC * HWP) + p0;
    const float* Xb = X + (size_t)(np + 32) * (CC * HWP) + p0;
    float* Ya = Y + (size_t)np * (CC * HWP) + p0;
    float* Yb = Y + (size_t)(np + 32) * (CC * HWP) + p0;

    const int ty = tid >> 5, tx = tid & 31;
    const int kkA = tid >> 5;          // 0..7
    const int gA = tid & 31;

    const float* s0 = (gA < 16) ? (Xa + (size_t)kkA * HWP + gA * 4)
                                : (Xb + (size_t)kkA * HWP + (gA - 16) * 4);
    const float* s1 = (gA < 16) ? (Xa + (size_t)(kkA + 8) * HWP + gA * 4)
                                : (Xb + (size_t)(kkA + 8) * HWP + (gA - 16) * 4);
    unsigned xb;
    {
        unsigned long long a64 = __cvta_generic_to_shared(Xs);
        xb = (unsigned)a64;
    }
    const unsigned x_off0 = (kkA * 128 + gA * 4) * 4;
    const unsigned x_off1 = ((kkA + 8) * 128 + gA * 4) * 4;

    // prologue: 3 stages in flight
#pragma unroll
    for (int t = 0; t < 3; ++t) {
        unsigned b = xb + (unsigned)(t * 2048 * 4);
        cpa16(b + x_off0, s0 + (size_t)t * 16 * HWP);
        cpa16(b + x_off1, s1 + (size_t)t * 16 * HWP);
        cpcommit();
    }

    if (tid < CC) bias_s[tid] = d_bias2[tid];
    {   // load full wmT (overlapped with cp.async of first tiles)
        const float4* Wg = (const float4*)d_wmT;
        float4* Wsm = (float4*)Ws;
#pragma unroll
        for (int i = tid; i < CC * CC / 4; i += 256) Wsm[i] = Wg[i];
    }

    unsigned long long acc[8][4];
#pragma unroll
    for (int i = 0; i < 8; i++)
#pragma unroll
        for (int jj = 0; jj < 4; jj++) acc[i][jj] = 0ull;

    for (int t = 0; t < 8; ++t) {
        cpwait<2>();
        __syncthreads();            // tile t visible to all; Ws ready (t=0)
        const float* B = Xs + (t % 3) * 2048;
        const float* Wrow = Ws + t * 16 * CC;
#pragma unroll
        for (int k = 0; k < 16; ++k) {
            const ulonglong2* wp = (const ulonglong2*)(Wrow + k * CC + ty * 16);
            ulonglong2 aA = wp[0], aB = wp[1], aC = wp[2], aD = wp[3];
            float4 bv = *(const float4*)(B + k * 128 + tx * 4);
            unsigned long long b0 = pk(bv.x, bv.x);
            unsigned long long b1 = pk(bv.y, bv.y);
            unsigned long long b2 = pk(bv.z, bv.z);
            unsigned long long b3 = pk(bv.w, bv.w);
            unsigned long long ap[8] = {aA.x, aA.y, aB.x, aB.y, aC.x, aC.y, aD.x, aD.y};
#pragma unroll
            for (int ip = 0; ip < 8; ip++) {
                fma2(acc[ip][0], ap[ip], b0);
                fma2(acc[ip][1], ap[ip], b1);
                fma2(acc[ip][2], ap[ip], b2);
                fma2(acc[ip][3], ap[ip], b3);
            }
        }
        __syncthreads();            // all done reading buf t%3
        if (t + 3 < 8) {
            unsigned b = xb + (unsigned)((t % 3) * 2048 * 4);
            cpa16(b + x_off0, s0 + (size_t)(t + 3) * 16 * HWP);
            cpa16(b + x_off1, s1 + (size_t)(t + 3) * 16 * HWP);
        }
        cpcommit();
    }

    float* baseY = (tx < 16) ? Ya : Yb;
    const int off = (tx < 16) ? tx * 4 : (tx - 16) * 4;
#pragma unroll
    for (int ip = 0; ip < 8; ip++) {
        float l0, h0, l1, h1, l2, h2, l3, h3;
        unpk(acc[ip][0], l0, h0); unpk(acc[ip][1], l1, h1);
        unpk(acc[ip][2], l2, h2); unpk(acc[ip][3], l3, h3);
        const int r0 = ty * 16 + 2 * ip;
        const float b0 = bias_s[r0], b1 = bias_s[r0 + 1];
        *(float4*)(baseY + (size_t)r0 * HWP + off)       = make_float4(l0 + b0, l1 + b0, l2 + b0, l3 + b0);
        *(float4*)(baseY + (size_t)(r0 + 1) * HWP + off) = make_float4(h0 + b1, h1 + b1, h2 + b1, h3 + b1);
    }
}

// ---------------- launch ----------------
extern "C" void kernel_launch(void* const* d_in, const int* in_sizes, int n_in,
                              void* d_out, int out_size) {
    const float* X = (const float*)d_in[0];
    const float* beta = (const float*)d_in[1];
    float* Y = (float*)d_out;
    cudaFuncSetAttribute(gram_kernel, cudaFuncAttributeMaxDynamicSharedMemorySize, GRAM_SMEM);
    cudaFuncSetAttribute(ns_kernel,   cudaFuncAttributeMaxDynamicSharedMemorySize, NS_SMEM);
    cudaFuncSetAttribute(whit_kernel, cudaFuncAttributeMaxDynamicSharedMemorySize, WHIT_SMEM);
    zero_kernel<<<1, 32>>>();
    gram_kernel<<<GBLK, 256, GRAM_SMEM>>>(X);
    reduce_kernel<<<65, 256>>>();
    ns_kernel<<<NSB, 512, NS_SMEM>>>(beta);
    whit_kernel<<<49 * 32, 256, WHIT_SMEM>>>(X, Y);
}

// round 6
// speedup vs baseline: 1.4761x; 1.2010x over previous
#include <cuda_runtime.h>
#include <cuda_bf16.h>

#define NN    64
#define CC    128
#define HWP   3136
#define MTOT  200704
#define EPSI  1e-5f
#define TITER 10
#define NSB   128
#define GCHUNK 784
#define GT    (GCHUNK/16)
#define GBLK  256

#define GRAM_SMEM (4*2048*4 + 2*16*132*4)

// whit smem layout (bytes, dynamic)
#define WPITCH 272            // 136 bf16 per wm row (128 + 8 pad)
#define XPITCH 144            // 72 bf16 per X row (64 + 8 pad)
#define S_WH   0
#define S_WL   (128*WPITCH)               // 34816
#define S_XH   (2*128*WPITCH)             // 69632
#define S_XL   (S_XH + 128*XPITCH)        // 88064
#define S_BIAS (S_XL + 128*XPITCH)        // 106496
#define WHIT_SMEM (S_BIAS + 128*4)        // 107008

// ---------------- scratch ----------------
__device__ float d_gpart[GBLK * CC * CC];
__device__ float d_cpart[GBLK * CC];
__device__ float d_gram[CC * CC];
__device__ float d_chsum[CC];
__device__ float d_Sig[CC * CC];
__device__ float d_P2[2][CC * CC];
__device__ __nv_bfloat16 d_wmh[CC * CC];   // wm hi, row-major [c][d]
__device__ __nv_bfloat16 d_wml[CC * CC];   // wm lo
__device__ float d_bias2[CC];
__device__ float d_trace;
__device__ unsigned g_bar;

// ---------------- fp32x2 helpers ----------------
__device__ __forceinline__ unsigned long long pk(float lo, float hi) {
    unsigned long long r; asm("mov.b64 %0, {%1, %2};" : "=l"(r) : "f"(lo), "f"(hi)); return r;
}
__device__ __forceinline__ void unpk(unsigned long long v, float &lo, float &hi) {
    asm("mov.b64 {%0, %1}, %2;" : "=f"(lo), "=f"(hi) : "l"(v));
}
__device__ __forceinline__ void fma2(unsigned long long &d, unsigned long long a, unsigned long long b) {
    asm("fma.rn.f32x2 %0, %1, %2, %0;" : "+l"(d) : "l"(a), "l"(b));
}
// ---------------- cp.async ----------------
__device__ __forceinline__ void cpa16(unsigned d, const float* s) {
    asm volatile("cp.async.cg.shared.global [%0], [%1], 16;" :: "r"(d), "l"(s));
}
__device__ __forceinline__ void cpcommit() { asm volatile("cp.async.commit_group;"); }
template<int N> __device__ __forceinline__ void cpwait() {
    asm volatile("cp.async.wait_group %0;" :: "n"(N));
}
__device__ __forceinline__ unsigned smem_u32(const void* p) {
    unsigned r; asm("{ .reg .u64 t; cvta.to.shared.u64 t, %1; cvt.u32.u64 %0, t; }" : "=r"(r) : "l"(p)); return r;
}
// ---------------- ldmatrix / mma.sync ----------------
__device__ __forceinline__ void ldsm_x4(unsigned &r0, unsigned &r1, unsigned &r2, unsigned &r3, unsigned a) {
    asm volatile("ldmatrix.sync.aligned.m8n8.x4.shared.b16 {%0,%1,%2,%3}, [%4];"
                 : "=r"(r0), "=r"(r1), "=r"(r2), "=r"(r3) : "r"(a));
}
__device__ __forceinline__ void ldsm_x2t(unsigned &r0, unsigned &r1, unsigned a) {
    asm volatile("ldmatrix.sync.aligned.m8n8.x2.trans.shared.b16 {%0,%1}, [%2];"
                 : "=r"(r0), "=r"(r1) : "r"(a));
}
__device__ __forceinline__ void mma_bf16(float* d, unsigned a0, unsigned a1, unsigned a2, unsigned a3,
                                         unsigned b0, unsigned b1) {
    asm volatile("mma.sync.aligned.m16n8k16.row.col.f32.bf16.bf16.f32 "
                 "{%0,%1,%2,%3}, {%4,%5,%6,%7}, {%8,%9}, {%0,%1,%2,%3};"
                 : "+f"(d[0]), "+f"(d[1]), "+f"(d[2]), "+f"(d[3])
                 : "r"(a0), "r"(a1), "r"(a2), "r"(a3), "r"(b0), "r"(b1));
}
__device__ __forceinline__ unsigned pkbf(float a, float b) {
    __nv_bfloat162 t(__float2bfloat16(a), __float2bfloat16(b));
    return *(unsigned*)&t;
}

// ---------------- kernel 0 ----------------
__global__ void zero_kernel() {
    if (threadIdx.x == 0) { d_trace = 0.f; g_bar = 0u; }
}

// ---------------- kernel 1: Gram partials (measured-good, unchanged) ----------------
__global__ void __launch_bounds__(256, 2) gram_kernel(const float* __restrict__ X) {
    extern __shared__ char smraw[];
    float* raw = (float*)smraw;
    float* As  = (float*)(smraw + 4 * 2048 * 4);
    __shared__ float chs[CC];
    const int tid = threadIdx.x;
    const int n = blockIdx.x >> 2;
    const int pbase = (blockIdx.x & 3) * GCHUNK;
    const float* Xn = X + (size_t)n * (CC * HWP) + pbase;
    const int cL = tid >> 2, q0 = (tid & 3) * 4, ty = tid >> 5, tx = tid & 31;

    if (tid < CC) chs[tid] = 0.f;
    unsigned long long acc[8][4];
#pragma unroll
    for (int i = 0; i < 8; i++)
#pragma unroll
        for (int j = 0; j < 4; j++) acc[i][j] = 0ull;
    float cs0 = 0.f, cs1 = 0.f;

    const float* g0 = Xn + (size_t)cL * HWP + q0;
    const float* g1 = Xn + (size_t)(cL + 64) * HWP + q0;
    unsigned rbase = smem_u32(raw);
    const unsigned r_off0 = (cL * 16 + q0) * 4;
    const unsigned r_off1 = ((cL + 64) * 16 + q0) * 4;
#pragma unroll
    for (int t = 0; t < 4; ++t) {
        unsigned b = rbase + (unsigned)(t * 2048 * 4);
        cpa16(b + r_off0, g0 + t * 16);
        cpa16(b + r_off1, g1 + t * 16);
        cpcommit();
    }
    cpwait<3>();
    {
        const float* rb = raw;
        float4 v0 = *(const float4*)(rb + cL * 16 + q0);
        float4 v1 = *(const float4*)(rb + (cL + 64) * 16 + q0);
        float* A = As;
        A[(q0+0)*132 + cL] = v0.x; A[(q0+1)*132 + cL] = v0.y;
        A[(q0+2)*132 + cL] = v0.z; A[(q0+3)*132 + cL] = v0.w;
        A[(q0+0)*132 + cL+64] = v1.x; A[(q0+1)*132 + cL+64] = v1.y;
        A[(q0+2)*132 + cL+64] = v1.z; A[(q0+3)*132 + cL+64] = v1.w;
        cs0 += (v0.x + v0.y) + (v0.z + v0.w);
        cs1 += (v1.x + v1.y) + (v1.z + v1.w);
    }
    __syncthreads();
    for (int t = 0; t < GT; ++t) {
        cpwait<2>();
        if (t + 1 < GT) {
            const float* rb = raw + ((t + 1) & 3) * 2048;
            float4 v0 = *(const float4*)(rb + cL * 16 + q0);
            float4 v1 = *(const float4*)(rb + (cL + 64) * 16 + q0);
            float* A = As + ((t + 1) & 1) * (16 * 132);
            A[(q0+0)*132 + cL] = v0.x; A[(q0+1)*132 + cL] = v0.y;
            A[(q0+2)*132 + cL] = v0.z; A[(q0+3)*132 + cL] = v0.w;
            A[(q0+0)*132 + cL+64] = v1.x; A[(q0+1)*132 + cL+64] = v1.y;
            A[(q0+2)*132 + cL+64] = v1.z; A[(q0+3)*132 + cL+64] = v1.w;
            cs0 += (v0.x + v0.y) + (v0.z + v0.w);
            cs1 += (v1.x + v1.y) + (v1.z + v1.w);
        }
        if (t + 4 < GT) {
            unsigned b = rbase + (unsigned)((t & 3) * 2048 * 4);
            cpa16(b + r_off0, g0 + (t + 4) * 16);
            cpa16(b + r_off1, g1 + (t + 4) * 16);
        }
        cpcommit();
        const float* A = As + (t & 1) * (16 * 132);
#pragma unroll
        for (int k = 0; k < 16; ++k) {
            const float* row = A + k * 132;
            const ulonglong2* wp = (const ulonglong2*)(row + ty * 16);
            ulonglong2 aA = wp[0], aB = wp[1], aC = wp[2], aD = wp[3];
            float4 bv = *(const float4*)(row + tx * 4);
            unsigned long long b0 = pk(bv.x, bv.x), b1 = pk(bv.y, bv.y);
            unsigned long long b2 = pk(bv.z, bv.z), b3 = pk(bv.w, bv.w);
            unsigned long long ap[8] = {aA.x, aA.y, aB.x, aB.y, aC.x, aC.y, aD.x, aD.y};
#pragma unroll
            for (int ip = 0; ip < 8; ip++) {
                fma2(acc[ip][0], ap[ip], b0); fma2(acc[ip][1], ap[ip], b1);
                fma2(acc[ip][2], ap[ip], b2); fma2(acc[ip][3], ap[ip], b3);
            }
        }
        __syncthreads();
    }
    atomicAdd(&chs[cL], cs0);
    atomicAdd(&chs[cL + 64], cs1);
    __syncthreads();
    if (tid < CC) d_cpart[blockIdx.x * CC + tid] = chs[tid];
    float* gp = d_gpart + (size_t)blockIdx.x * (CC * CC);
#pragma unroll
    for (int ip = 0; ip < 8; ip++) {
        int r0 = ty * 16 + 2 * ip;
        float l0,h0,l1,h1,l2,h2,l3,h3;
        unpk(acc[ip][0], l0, h0); unpk(acc[ip][1], l1, h1);
        unpk(acc[ip][2], l2, h2); unpk(acc[ip][3], l3, h3);
        *(float4*)(gp + r0 * CC + tx * 4)       = make_float4(l0, l1, l2, l3);
        *(float4*)(gp + (r0 + 1) * CC + tx * 4) = make_float4(h0, h1, h2, h3);
    }
}

// ---------------- kernel 2: reduce ----------------
__global__ void reduce_kernel() {
    const int bid = blockIdx.x, tid = threadIdx.x;
    if (bid < 64) {
        const int i = bid * 256 + tid;
        float s = 0.f;
#pragma unroll 8
        for (int b = 0; b < GBLK; b++) s += d_gpart[(size_t)b * (CC * CC) + i];
        d_gram[i] = s;
    } else if (tid < CC) {
        float s = 0.f;
#pragma unroll 8
        for (int b = 0; b < GBLK; b++) s += d_cpart[b * CC + tid];
        d_chsum[tid] = s;
    }
}

// ---------------- kernel 3: Newton-Schulz (direct-L2, ping-pong, 11 gsyncs) ----------------
__device__ __forceinline__ void gsync(unsigned &tgt) {
    __threadfence();
    __syncthreads();
    tgt += NSB;
    if (threadIdx.x == 0) {
        atomicAdd(&g_bar, 1u);
        while (*(volatile unsigned*)&g_bar < tgt) {}
    }
    __syncthreads();
}
__device__ __forceinline__ float rowmat(const float* __restrict__ v,
                                        const float* __restrict__ Mg, int j) {
    float a0 = 0.f, a1 = 0.f, a2 = 0.f, a3 = 0.f;
#pragma unroll
    for (int k = 0; k < CC; k += 4) {
        a0 = fmaf(v[k+0], __ldcg(&Mg[(k+0)*CC + j]), a0);
        a1 = fmaf(v[k+1], __ldcg(&Mg[(k+1)*CC + j]), a1);
        a2 = fmaf(v[k+2], __ldcg(&Mg[(k+2)*CC + j]), a2);
        a3 = fmaf(v[k+3], __ldcg(&Mg[(k+3)*CC + j]), a3);
    }
    return (a0 + a1) + (a2 + a3);
}
__global__ void __launch_bounds__(128, 1) ns_kernel(const float* __restrict__ beta) {
    __shared__ float mean_s[CC], pr_s[CC], t1_s[CC], t2_s[CC];
    __shared__ float rtr_s;
    const int r = blockIdx.x, j = threadIdx.x;

    mean_s[j] = d_chsum[j] * (1.f / (float)MTOT);
    __syncthreads();
    float sig = d_gram[r*CC + j] * (1.f / (float)MTOT) - mean_s[r] * mean_s[j]
                + ((j == r) ? EPSI : 0.f);
    __stcg(&d_Sig[r*CC + j], sig);
    __stcg(&d_P2[0][r*CC + j], (j == r) ? 1.f : 0.f);
    if (j == r) atomicAdd(&d_trace, sig);

    unsigned tgt = 0;
    gsync(tgt);
    if (j == 0) rtr_s = 1.f / *(volatile float*)&d_trace;
    __syncthreads();
    const float rtr = rtr_s;

    int cur = 0;
    for (int it = 0; it < TITER; ++it) {
        float prj = __ldcg(&d_P2[cur][r*CC + j]);
        pr_s[j] = prj;
        __syncthreads();
        t1_s[j] = rowmat(pr_s, d_P2[cur], j);
        __syncthreads();
        t2_s[j] = rowmat(t1_s, d_P2[cur], j);
        __syncthreads();
        float u = rowmat(t2_s, d_Sig, j);
        __stcg(&d_P2[1 - cur][r*CC + j], 1.5f * prj - 0.5f * rtr * u);
        gsync(tgt);
        cur ^= 1;
    }

    float w = __ldcg(&d_P2[cur][r*CC + j]) * sqrtf(rtr);
    __nv_bfloat16 wh = __float2bfloat16(w);
    float whf = __bfloat162float(wh);
    __nv_bfloat16 wl = __float2bfloat16(w - whf);
    d_wmh[r*CC + j] = wh;
    d_wml[r*CC + j] = wl;
    float wq = whf + __bfloat162float(wl);
    t1_s[j] = wq * mean_s[j];
    __syncthreads();
    for (int s = 64; s > 0; s >>= 1) {
        if (j < s) t1_s[j] += t1_s[j + s];
        __syncthreads();
    }
    if (j == 0) d_bias2[r] = beta[r] - t1_s[0];
}

// ---------------- kernel 4: whitening via mma.sync bf16 split (tensor path) ------
// Grid 3136 = 64 img x 49 p-tiles(64). Block: 128(c) x 64(p). Warp w: rows 16w..16w+15.
// 3 passes: wm_hi*x_hi + wm_hi*x_lo + wm_lo*x_hi into fp32 accumulators.
__global__ void __launch_bounds__(256) whit_kernel(const float* __restrict__ X,
                                                   float* __restrict__ Y) {
    extern __shared__ char sm[];
    const int tid = threadIdx.x, wid = tid >> 5, lane = tid & 31;
    const unsigned smb = smem_u32(sm);
    const int n = blockIdx.x / 49, pt = blockIdx.x % 49, p0 = pt * 64;

    // stage wm hi/lo into padded smem (row-major [c][d], pitch WPITCH bytes)
    {
        const unsigned* wh = (const unsigned*)d_wmh;
        const unsigned* wl = (const unsigned*)d_wml;
#pragma unroll 8
        for (int i = tid; i < 8192; i += 256) {
            int c = i >> 6, dp = i & 63;
            unsigned off = (unsigned)(c * WPITCH + dp * 4);
            *(unsigned*)(sm + S_WH + off) = wh[i];
            *(unsigned*)(sm + S_WL + off) = wl[i];
        }
    }
    if (tid < 128) ((float*)(sm + S_BIAS))[tid] = d_bias2[tid];

    // convert X tile [128 d][64 p] -> bf16 hi/lo (pitch XPITCH bytes)
    {
        const int r = tid >> 2, q = tid & 3;
#pragma unroll
        for (int h = 0; h < 2; ++h) {
            const int row = r + h * 64;
            const float* xp = X + ((size_t)n * CC + row) * HWP + p0 + q * 16;
            unsigned hi[8], lo[8];
#pragma unroll
            for (int i = 0; i < 4; ++i) {
                float4 v = *(const float4*)(xp + 4 * i);
                __nv_bfloat16 hx = __float2bfloat16(v.x), hy = __float2bfloat16(v.y);
                __nv_bfloat16 hz = __float2bfloat16(v.z), hw = __float2bfloat16(v.w);
                __nv_bfloat162 hp0(hx, hy), hp1(hz, hw);
                hi[2*i]   = *(unsigned*)&hp0;
                hi[2*i+1] = *(unsigned*)&hp1;
                lo[2*i]   = pkbf(v.x - __bfloat162float(hx), v.y - __bfloat162float(hy));
                lo[2*i+1] = pkbf(v.z - __bfloat162float(hz), v.w - __bfloat162float(hw));
            }
            const unsigned off = (unsigned)(row * XPITCH + q * 32);
            *(uint4*)(sm + S_XH + off)      = make_uint4(hi[0], hi[1], hi[2], hi[3]);
            *(uint4*)(sm + S_XH + off + 16) = make_uint4(hi[4], hi[5], hi[6], hi[7]);
            *(uint4*)(sm + S_XL + off)      = make_uint4(lo[0], lo[1], lo[2], lo[3]);
            *(uint4*)(sm + S_XL + off + 16) = make_uint4(lo[4], lo[5], lo[6], lo[7]);
        }
    }
    __syncthreads();

    float acc[8][4];
#pragma unroll
    for (int j = 0; j < 8; ++j)
#pragma unroll
        for (int q = 0; q < 4; ++q) acc[j][q] = 0.f;

    const unsigned arow = (unsigned)(wid * 16 + (lane & 15));
    const unsigned acol = (unsigned)((lane >> 4) * 16);   // 8 bf16 * 2B
    const unsigned brln = (unsigned)(lane & 15);

#pragma unroll
    for (int kt = 0; kt < 8; ++kt) {
        const int k0 = kt * 16;
        unsigned aaddr = smb + S_WH + arow * WPITCH + (unsigned)(k0 * 2) + acol;
        unsigned ah0, ah1, ah2, ah3, al0, al1, al2, al3;
        ldsm_x4(ah0, ah1, ah2, ah3, aaddr);
        ldsm_x4(al0, al1, al2, al3, aaddr + (S_WL - S_WH));
        const unsigned bbase = smb + S_XH + (unsigned)((k0 + brln) * XPITCH);
#pragma unroll
        for (int j = 0; j < 8; ++j) {
            unsigned bh0, bh1, bl0, bl1;
            ldsm_x2t(bh0, bh1, bbase + j * 16);
            ldsm_x2t(bl0, bl1, bbase + j * 16 + (S_XL - S_XH));
            mma_bf16(acc[j], ah0, ah1, ah2, ah3, bh0, bh1);
            mma_bf16(acc[j], ah0, ah1, ah2, ah3, bl0, bl1);
            mma_bf16(acc[j], al0, al1, al2, al3, bh0, bh1);
        }
    }

    // epilogue: D frag -> Y + bias
    const int row0 = wid * 16 + (lane >> 2);
    const float b0 = ((const float*)(sm + S_BIAS))[row0];
    const float b1 = ((const float*)(sm + S_BIAS))[row0 + 8];
    float* y0 = Y + ((size_t)n * CC + row0) * HWP + p0 + (lane & 3) * 2;
#pragma unroll
    for (int j = 0; j < 8; ++j) {
        *(float2*)(y0 + 8 * j)            = make_float2(acc[j][0] + b0, acc[j][1] + b0);
        *(float2*)(y0 + 8 * j + 8 * HWP)  = make_float2(acc[j][2] + b1, acc[j][3] + b1);
    }
}

// ---------------- launch ----------------
extern "C" void kernel_launch(void* const* d_in, const int* in_sizes, int n_in,
                              void* d_out, int out_size) {
    const float* X = (const float*)d_in[0];
    const float* beta = (const float*)d_in[1];
    float* Y = (float*)d_out;
    cudaFuncSetAttribute(gram_kernel, cudaFuncAttributeMaxDynamicSharedMemorySize, GRAM_SMEM);
    cudaFuncSetAttribute(whit_kernel, cudaFuncAttributeMaxDynamicSharedMemorySize, WHIT_SMEM);
    zero_kernel<<<1, 32>>>();
    gram_kernel<<<GBLK, 256, GRAM_SMEM>>>(X);
    reduce_kernel<<<65, 256>>>();
    ns_kernel<<<NSB, 128>>>(beta);
    whit_kernel<<<49 * 64, 256, WHIT_SMEM>>>(X, Y);
}

// round 7
// speedup vs baseline: 1.9227x; 1.3026x over previous
#include <cuda_runtime.h>
#include <cuda_bf16.h>

#define NN    64
#define CC    128
#define HWP   3136
#define MTOT  200704
#define EPSI  1e-5f
#define TITER 10
#define NSB   128
#define GCHUNK 784
#define GBLK  256

// gram smem: [buf 0/1][prec hi/lo][128 rows][48B: 32B data + 16B pad]
#define PITCHB 48
#define GPREC  (128 * PITCHB)       // 6144
#define GBUF   (2 * GPREC)          // 12288

// whit smem layout (bytes, dynamic)
#define WPITCH 272
#define XPITCH 144
#define S_WH   0
#define S_WL   (128*WPITCH)
#define S_XH   (2*128*WPITCH)
#define S_XL   (S_XH + 128*XPITCH)
#define S_BIAS (S_XL + 128*XPITCH)
#define WHIT_SMEM (S_BIAS + 128*4)

// ---------------- scratch ----------------
__device__ float d_gpart[GBLK * CC * CC];
__device__ float d_cpart[GBLK * CC];
__device__ float d_gram[CC * CC];
__device__ float d_chsum[CC];
__device__ float d_Sig[CC * CC];
__device__ float d_P2[2][CC * CC];
__device__ __nv_bfloat16 d_wmh[CC * CC];
__device__ __nv_bfloat16 d_wml[CC * CC];
__device__ float d_bias2[CC];
__device__ float d_trace;
__device__ unsigned g_bar;

// ---------------- helpers ----------------
__device__ __forceinline__ unsigned smem_u32(const void* p) {
    unsigned r; asm("{ .reg .u64 t; cvta.to.shared.u64 t, %1; cvt.u32.u64 %0, t; }" : "=r"(r) : "l"(p)); return r;
}
__device__ __forceinline__ void ldsm_x4(unsigned &r0, unsigned &r1, unsigned &r2, unsigned &r3, unsigned a) {
    asm volatile("ldmatrix.sync.aligned.m8n8.x4.shared.b16 {%0,%1,%2,%3}, [%4];"
                 : "=r"(r0), "=r"(r1), "=r"(r2), "=r"(r3) : "r"(a));
}
__device__ __forceinline__ void ldsm_x2t(unsigned &r0, unsigned &r1, unsigned a) {
    asm volatile("ldmatrix.sync.aligned.m8n8.x2.trans.shared.b16 {%0,%1}, [%2];"
                 : "=r"(r0), "=r"(r1) : "r"(a));
}
__device__ __forceinline__ void mma_bf16(float* d, unsigned a0, unsigned a1, unsigned a2, unsigned a3,
                                         unsigned b0, unsigned b1) {
    asm volatile("mma.sync.aligned.m16n8k16.row.col.f32.bf16.bf16.f32 "
                 "{%0,%1,%2,%3}, {%4,%5,%6,%7}, {%8,%9}, {%0,%1,%2,%3};"
                 : "+f"(d[0]), "+f"(d[1]), "+f"(d[2]), "+f"(d[3])
                 : "r"(a0), "r"(a1), "r"(a2), "r"(a3), "r"(b0), "r"(b1));
}
__device__ __forceinline__ unsigned pkbf(float a, float b) {
    __nv_bfloat162 t(__float2bfloat16(a), __float2bfloat16(b));
    return *(unsigned*)&t;
}

// ---------------- kernel 0 ----------------
__global__ void zero_kernel() {
    if (threadIdx.x == 0) { d_trace = 0.f; g_bar = 0u; }
}

// ---------------- kernel 1: Gram via mma.sync bf16 split ----------------
// 256 CTAs = 64 img x 4 chunks(784 px). Per CTA full 128x128 gram over its chunk.
// Per k16: convert fp32->bf16 hi/lo into buf[t&1], 1 sync, reg-prefetch t+1, 48 MMAs/warp.
__global__ void __launch_bounds__(256) gram_kernel(const float* __restrict__ X) {
    __shared__ __align__(16) char sm[2 * GBUF];   // 24576 B
    __shared__ float chs[CC];
    const int tid = threadIdx.x, wid = tid >> 5, lane = tid & 31;
    const unsigned smb = smem_u32(sm);
    const int n = blockIdx.x >> 2;
    const int pbase = (blockIdx.x & 3) * GCHUNK;
    const float* Xn = X + (size_t)n * (CC * HWP) + pbase;

    const int r = tid >> 1, q = tid & 1;           // staging: row, 8-float half
    const float* gsrc = Xn + (size_t)r * HWP + q * 8;
    if (tid < CC) chs[tid] = 0.f;

    float acc[16][4];
#pragma unroll
    for (int j = 0; j < 16; ++j)
#pragma unroll
        for (int z = 0; z < 4; ++z) acc[j][z] = 0.f;
    float cs = 0.f;

    // ldmatrix addresses
    const unsigned a_off = (unsigned)((wid * 16 + (lane & 15)) * PITCHB + (lane >> 4) * 16);
    const unsigned b_row = (unsigned)((lane >> 4) * 8 + (lane & 7));
    const unsigned b_koff = (unsigned)(((lane >> 3) & 1) * 16);
    const unsigned st_off = (unsigned)(r * PITCHB + q * 16);

    float4 pv0 = *(const float4*)(gsrc);
    float4 pv1 = *(const float4*)(gsrc + 4);

    for (int t = 0; t < 49; ++t) {
        // convert + store into buf[t&1]
        char* base = sm + (t & 1) * GBUF;
        {
            unsigned h0 = pkbf(pv0.x, pv0.y), h1 = pkbf(pv0.z, pv0.w);
            unsigned h2 = pkbf(pv1.x, pv1.y), h3 = pkbf(pv1.z, pv1.w);
            float hx, hy, hz, hw;
            __nv_bfloat162 t0 = *(__nv_bfloat162*)&h0; hx = __bfloat162float(t0.x); hy = __bfloat162float(t0.y);
            __nv_bfloat162 t1 = *(__nv_bfloat162*)&h1; hz = __bfloat162float(t1.x); hw = __bfloat162float(t1.y);
            unsigned l0 = pkbf(pv0.x - hx, pv0.y - hy), l1 = pkbf(pv0.z - hz, pv0.w - hw);
            __nv_bfloat162 t2 = *(__nv_bfloat162*)&h2; hx = __bfloat162float(t2.x); hy = __bfloat162float(t2.y);
            __nv_bfloat162 t3 = *(__nv_bfloat162*)&h3; hz = __bfloat162float(t3.x); hw = __bfloat162float(t3.y);
            unsigned l2 = pkbf(pv1.x - hx, pv1.y - hy), l3 = pkbf(pv1.z - hz, pv1.w - hw);
            *(uint4*)(base + st_off)         = make_uint4(h0, h1, h2, h3);
            *(uint4*)(base + GPREC + st_off) = make_uint4(l0, l1, l2, l3);
            cs += ((pv0.x + pv0.y) + (pv0.z + pv0.w)) + ((pv1.x + pv1.y) + (pv1.z + pv1.w));
        }
        __syncthreads();
        if (t < 48) {
            pv0 = *(const float4*)(gsrc + (t + 1) * 16);
            pv1 = *(const float4*)(gsrc + (t + 1) * 16 + 4);
        }
        const unsigned tb = smb + (unsigned)((t & 1) * GBUF);
        unsigned ah0, ah1, ah2, ah3, al0, al1, al2, al3;
        ldsm_x4(ah0, ah1, ah2, ah3, tb + a_off);
        ldsm_x4(al0, al1, al2, al3, tb + GPREC + a_off);
#pragma unroll
        for (int p = 0; p < 8; ++p) {
            const unsigned ba = tb + (unsigned)((16 * p + b_row) * PITCHB) + b_koff;
            unsigned bh0, bh1, bh2, bh3, bl0, bl1, bl2, bl3;
            ldsm_x4(bh0, bh1, bh2, bh3, ba);
            ldsm_x4(bl0, bl1, bl2, bl3, ba + GPREC);
            mma_bf16(acc[2*p],   ah0, ah1, ah2, ah3, bh0, bh1);
            mma_bf16(acc[2*p+1], ah0, ah1, ah2, ah3, bh2, bh3);
            mma_bf16(acc[2*p],   ah0, ah1, ah2, ah3, bl0, bl1);
            mma_bf16(acc[2*p+1], ah0, ah1, ah2, ah3, bl2, bl3);
            mma_bf16(acc[2*p],   al0, al1, al2, al3, bh0, bh1);
            mma_bf16(acc[2*p+1], al0, al1, al2, al3, bh2, bh3);
        }
    }

    __syncthreads();
    atomicAdd(&chs[r], cs);
    __syncthreads();
    if (tid < CC) d_cpart[blockIdx.x * CC + tid] = chs[tid];

    float* gp = d_gpart + (size_t)blockIdx.x * (CC * CC);
    const int row0 = wid * 16 + (lane >> 2);
#pragma unroll
    for (int j = 0; j < 16; ++j) {
        const int col = j * 8 + (lane & 3) * 2;
        *(float2*)(gp + row0 * CC + col)       = make_float2(acc[j][0], acc[j][1]);
        *(float2*)(gp + (row0 + 8) * CC + col) = make_float2(acc[j][2], acc[j][3]);
    }
}

// ---------------- kernel 2: reduce ----------------
__global__ void reduce_kernel() {
    const int bid = blockIdx.x, tid = threadIdx.x;
    if (bid < 64) {
        const int i = bid * 256 + tid;
        float s = 0.f;
#pragma unroll 8
        for (int b = 0; b < GBLK; b++) s += d_gpart[(size_t)b * (CC * CC) + i];
        d_gram[i] = s;
    } else if (tid < CC) {
        float s = 0.f;
#pragma unroll 8
        for (int b = 0; b < GBLK; b++) s += d_cpart[b * CC + tid];
        d_chsum[tid] = s;
    }
}

// ---------------- kernel 3: Newton-Schulz (measured-good) ----------------
__device__ __forceinline__ void gsync(unsigned &tgt) {
    __threadfence();
    __syncthreads();
    tgt += NSB;
    if (threadIdx.x == 0) {
        atomicAdd(&g_bar, 1u);
        while (*(volatile unsigned*)&g_bar < tgt) {}
    }
    __syncthreads();
}
__device__ __forceinline__ float rowmat(const float* __restrict__ v,
                                        const float* __restrict__ Mg, int j) {
    float a0 = 0.f, a1 = 0.f, a2 = 0.f, a3 = 0.f;
#pragma unroll
    for (int k = 0; k < CC; k += 4) {
        a0 = fmaf(v[k+0], __ldcg(&Mg[(k+0)*CC + j]), a0);
        a1 = fmaf(v[k+1], __ldcg(&Mg[(k+1)*CC + j]), a1);
        a2 = fmaf(v[k+2], __ldcg(&Mg[(k+2)*CC + j]), a2);
        a3 = fmaf(v[k+3], __ldcg(&Mg[(k+3)*CC + j]), a3);
    }
    return (a0 + a1) + (a2 + a3);
}
__global__ void __launch_bounds__(128, 1) ns_kernel(const float* __restrict__ beta) {
    __shared__ float mean_s[CC], pr_s[CC], t1_s[CC], t2_s[CC];
    __shared__ float rtr_s;
    const int r = blockIdx.x, j = threadIdx.x;

    mean_s[j] = d_chsum[j] * (1.f / (float)MTOT);
    __syncthreads();
    float sig = d_gram[r*CC + j] * (1.f / (float)MTOT) - mean_s[r] * mean_s[j]
                + ((j == r) ? EPSI : 0.f);
    __stcg(&d_Sig[r*CC + j], sig);
    __stcg(&d_P2[0][r*CC + j], (j == r) ? 1.f : 0.f);
    if (j == r) atomicAdd(&d_trace, sig);

    unsigned tgt = 0;
    gsync(tgt);
    if (j == 0) rtr_s = 1.f / *(volatile float*)&d_trace;
    __syncthreads();
    const float rtr = rtr_s;

    int cur = 0;
    for (int it = 0; it < TITER; ++it) {
        float prj = __ldcg(&d_P2[cur][r*CC + j]);
        pr_s[j] = prj;
        __syncthreads();
        t1_s[j] = rowmat(pr_s, d_P2[cur], j);
        __syncthreads();
        t2_s[j] = rowmat(t1_s, d_P2[cur], j);
        __syncthreads();
        float u = rowmat(t2_s, d_Sig, j);
        __stcg(&d_P2[1 - cur][r*CC + j], 1.5f * prj - 0.5f * rtr * u);
        gsync(tgt);
        cur ^= 1;
    }

    float w = __ldcg(&d_P2[cur][r*CC + j]) * sqrtf(rtr);
    __nv_bfloat16 wh = __float2bfloat16(w);
    float whf = __bfloat162float(wh);
    __nv_bfloat16 wl = __float2bfloat16(w - whf);
    d_wmh[r*CC + j] = wh;
    d_wml[r*CC + j] = wl;
    float wq = whf + __bfloat162float(wl);
    t1_s[j] = wq * mean_s[j];
    __syncthreads();
    for (int s = 64; s > 0; s >>= 1) {
        if (j < s) t1_s[j] += t1_s[j + s];
        __syncthreads();
    }
    if (j == 0) d_bias2[r] = beta[r] - t1_s[0];
}

// ---------------- kernel 4: whitening via mma.sync bf16 split (measured-good) ---
__global__ void __launch_bounds__(256) whit_kernel(const float* __restrict__ X,
                                                   float* __restrict__ Y) {
    extern __shared__ char sm[];
    const int tid = threadIdx.x, wid = tid >> 5, lane = tid & 31;
    const unsigned smb = smem_u32(sm);
    const int n = blockIdx.x / 49, pt = blockIdx.x % 49, p0 = pt * 64;

    {
        const unsigned* wh = (const unsigned*)d_wmh;
        const unsigned* wl = (const unsigned*)d_wml;
#pragma unroll 8
        for (int i = tid; i < 8192; i += 256) {
            int c = i >> 6, dp = i & 63;
            unsigned off = (unsigned)(c * WPITCH + dp * 4);
            *(unsigned*)(sm + S_WH + off) = wh[i];
            *(unsigned*)(sm + S_WL + off) = wl[i];
        }
    }
    if (tid < 128) ((float*)(sm + S_BIAS))[tid] = d_bias2[tid];

    {
        const int r = tid >> 2, q = tid & 3;
#pragma unroll
        for (int h = 0; h < 2; ++h) {
            const int row = r + h * 64;
            const float* xp = X + ((size_t)n * CC + row) * HWP + p0 + q * 16;
            unsigned hi[8], lo[8];
#pragma unroll
            for (int i = 0; i < 4; ++i) {
                float4 v = *(const float4*)(xp + 4 * i);
                __nv_bfloat16 hx = __float2bfloat16(v.x), hy = __float2bfloat16(v.y);
                __nv_bfloat16 hz = __float2bfloat16(v.z), hw = __float2bfloat16(v.w);
                __nv_bfloat162 hp0(hx, hy), hp1(hz, hw);
                hi[2*i]   = *(unsigned*)&hp0;
                hi[2*i+1] = *(unsigned*)&hp1;
                lo[2*i]   = pkbf(v.x - __bfloat162float(hx), v.y - __bfloat162float(hy));
                lo[2*i+1] = pkbf(v.z - __bfloat162float(hz), v.w - __bfloat162float(hw));
            }
            const unsigned off = (unsigned)(row * XPITCH + q * 32);
            *(uint4*)(sm + S_XH + off)      = make_uint4(hi[0], hi[1], hi[2], hi[3]);
            *(uint4*)(sm + S_XH + off + 16) = make_uint4(hi[4], hi[5], hi[6], hi[7]);
            *(uint4*)(sm + S_XL + off)      = make_uint4(lo[0], lo[1], lo[2], lo[3]);
            *(uint4*)(sm + S_XL + off + 16) = make_uint4(lo[4], lo[5], lo[6], lo[7]);
        }
    }
    __syncthreads();

    float acc[8][4];
#pragma unroll
    for (int j = 0; j < 8; ++j)
#pragma unroll
        for (int q = 0; q < 4; ++q) acc[j][q] = 0.f;

    const unsigned arow = (unsigned)(wid * 16 + (lane & 15));
    const unsigned acol = (unsigned)((lane >> 4) * 16);
    const unsigned brln = (unsigned)(lane & 15);

#pragma unroll
    for (int kt = 0; kt < 8; ++kt) {
        const int k0 = kt * 16;
        unsigned aaddr = smb + S_WH + arow * WPITCH + (unsigned)(k0 * 2) + acol;
        unsigned ah0, ah1, ah2, ah3, al0, al1, al2, al3;
        ldsm_x4(ah0, ah1, ah2, ah3, aaddr);
        ldsm_x4(al0, al1, al2, al3, aaddr + (S_WL - S_WH));
        const unsigned bbase = smb + S_XH + (unsigned)((k0 + brln) * XPITCH);
#pragma unroll
        for (int j = 0; j < 8; ++j) {
            unsigned bh0, bh1, bl0, bl1;
            ldsm_x2t(bh0, bh1, bbase + j * 16);
            ldsm_x2t(bl0, bl1, bbase + j * 16 + (S_XL - S_XH));
            mma_bf16(acc[j], ah0, ah1, ah2, ah3, bh0, bh1);
            mma_bf16(acc[j], ah0, ah1, ah2, ah3, bl0, bl1);
            mma_bf16(acc[j], al0, al1, al2, al3, bh0, bh1);
        }
    }

    const int row0 = wid * 16 + (lane >> 2);
    const float b0 = ((const float*)(sm + S_BIAS))[row0];
    const float b1 = ((const float*)(sm + S_BIAS))[row0 + 8];
    float* y0 = Y + ((size_t)n * CC + row0) * HWP + p0 + (lane & 3) * 2;
#pragma unroll
    for (int j = 0; j < 8; ++j) {
        *(float2*)(y0 + 8 * j)            = make_float2(acc[j][0] + b0, acc[j][1] + b0);
        *(float2*)(y0 + 8 * j + 8 * HWP)  = make_float2(acc[j][2] + b1, acc[j][3] + b1);
    }
}

// ---------------- launch ----------------
extern "C" void kernel_launch(void* const* d_in, const int* in_sizes, int n_in,
                              void* d_out, int out_size) {
    const float* X = (const float*)d_in[0];
    const float* beta = (const float*)d_in[1];
    float* Y = (float*)d_out;
    cudaFuncSetAttribute(whit_kernel, cudaFuncAttributeMaxDynamicSharedMemorySize, WHIT_SMEM);
    zero_kernel<<<1, 32>>>();
    gram_kernel<<<GBLK, 256>>>(X);
    reduce_kernel<<<65, 256>>>();
    ns_kernel<<<NSB, 128>>>(beta);
    whit_kernel<<<49 * 64, 256, WHIT_SMEM>>>(X, Y);
}